// round 2
// baseline (speedup 1.0000x reference)
#include <cuda_runtime.h>
#include <cstdint>

#define N_MAX 50000
#define E_MAX 800000
#define D 128

// ---- scratch (__device__ globals; no cudaMalloc allowed) -------------------
__device__ float g_agg[N_MAX * D];     // nd-scaled aggregation result [N,128]
__device__ int   g_deg_out[N_MAX];
__device__ int   g_deg_in[N_MAX];
__device__ int   g_off[N_MAX + 1];     // CSR offsets by dst
__device__ int   g_cursor[N_MAX];
__device__ int   g_esrc[E_MAX];        // src node of each edge, bucketed by dst
__device__ float g_ns[N_MAX];          // rsqrt(max(deg_out,1))
__device__ float g_nd[N_MAX];          // rsqrt(max(deg_in,1))
__device__ float g_Wfused[D * D];      // W_conv @ W_aggr[0:128]
__device__ float g_bias[D];            // b_conv @ Wa1 + b_aggr

// packed f32x2 helpers (sm_103a)
#define FMA2(acc, a, b) \
    asm("fma.rn.f32x2 %0, %1, %2, %0;" : "+l"(acc) : "l"(a), "l"(b))
#define ADD2(dst, a, b) \
    asm("add.rn.f32x2 %0, %1, %2;" : "=l"(dst) : "l"(a), "l"(b))
#define PACKDUP(dst, x) \
    asm("mov.b64 %0, {%1, %1};" : "=l"(dst) : "r"(__float_as_uint(x)))

// ---------------------------------------------------------------------------
// K0: zero degree counters
__global__ void zero_kernel(int n) {
    int i = blockIdx.x * blockDim.x + threadIdx.x;
    if (i < n) { g_deg_out[i] = 0; g_deg_in[i] = 0; }
}

// K1: degree histograms
__global__ void deg_kernel(const int* __restrict__ src,
                           const int* __restrict__ dst, int E) {
    int i = blockIdx.x * blockDim.x + threadIdx.x;
    if (i < E) {
        atomicAdd(&g_deg_out[src[i]], 1);
        atomicAdd(&g_deg_in[dst[i]], 1);
    }
}

// K2: single-block exclusive scan of deg_in -> g_off/g_cursor; also ns/nd.
__global__ __launch_bounds__(1024) void scan_kernel(int n) {
    __shared__ int part[1024];
    int t = threadIdx.x;
    int chunk = (n + 1023) >> 10;
    int beg = t * chunk;
    int end = min(beg + chunk, n);
    int s = 0;
    for (int i = beg; i < end; i++) s += g_deg_in[i];
    part[t] = s;
    __syncthreads();
    // Hillis-Steele inclusive scan over 1024 partials
    for (int off = 1; off < 1024; off <<= 1) {
        int v = (t >= off) ? part[t - off] : 0;
        __syncthreads();
        part[t] += v;
        __syncthreads();
    }
    int run = (t == 0) ? 0 : part[t - 1];
    for (int i = beg; i < end; i++) {
        g_off[i] = run;
        g_cursor[i] = run;
        run += g_deg_in[i];
    }
    if (t == 1023) g_off[n] = part[1023];

    for (int i = t; i < n; i += 1024) {
        g_ns[i] = rsqrtf(fmaxf((float)g_deg_out[i], 1.0f));
        g_nd[i] = rsqrtf(fmaxf((float)g_deg_in[i], 1.0f));
    }
}

// K3: bucket edges by dst
__global__ void bucket_kernel(const int* __restrict__ src,
                              const int* __restrict__ dst, int E) {
    int e = blockIdx.x * blockDim.x + threadIdx.x;
    if (e < E) {
        int d = dst[e];
        int p = atomicAdd(&g_cursor[d], 1);
        g_esrc[p] = src[e];
    }
}

// K4: precompute W_fused = Wc @ Wa1 and bias = b_conv @ Wa1 + b_aggr
__global__ void fuse_kernel(const float* __restrict__ Wc,
                            const float* __restrict__ Wa,
                            const float* __restrict__ bc,
                            const float* __restrict__ ba) {
    int j = threadIdx.x;
    if (blockIdx.x < D) {
        int i = blockIdx.x;
        float s = 0.f;
#pragma unroll 8
        for (int k = 0; k < D; k++) s += Wc[i * D + k] * Wa[k * D + j];
        g_Wfused[i * D + j] = s;
    } else {
        float s = ba[j];
#pragma unroll 8
        for (int k = 0; k < D; k++) s += bc[k] * Wa[k * D + j];
        g_bias[j] = s;
    }
}

// K5: CSR aggregation — one warp per dst node, register accumulation.
// g_agg[i] = nd_i * sum_{j in bucket(i)} ns[src_j] * X[src_j]
__global__ __launch_bounds__(256) void aggregate_kernel(
    const float4* __restrict__ X4, int n) {
    int warp = (blockIdx.x * 256 + threadIdx.x) >> 5;
    int lane = threadIdx.x & 31;
    if (warp >= n) return;
    int beg = g_off[warp];
    int end = g_off[warp + 1];

    float4 acc = make_float4(0.f, 0.f, 0.f, 0.f);
    int j = beg;
    for (; j + 1 < end; j += 2) {
        int s0 = g_esrc[j];
        int s1 = g_esrc[j + 1];
        float w0 = g_ns[s0];
        float w1 = g_ns[s1];
        float4 v0 = X4[s0 * 32 + lane];
        float4 v1 = X4[s1 * 32 + lane];
        acc.x += v0.x * w0 + v1.x * w1;
        acc.y += v0.y * w0 + v1.y * w1;
        acc.z += v0.z * w0 + v1.z * w1;
        acc.w += v0.w * w0 + v1.w * w1;
    }
    if (j < end) {
        int s0 = g_esrc[j];
        float w0 = g_ns[s0];
        float4 v0 = X4[s0 * 32 + lane];
        acc.x += v0.x * w0;
        acc.y += v0.y * w0;
        acc.z += v0.z * w0;
        acc.w += v0.w * w0;
    }
    float nd = g_nd[warp];
    acc.x *= nd; acc.y *= nd; acc.z *= nd; acc.w *= nd;
    ((float4*)g_agg)[warp * 32 + lane] = acc;
}

// K6: out = agg @ W_fused + X @ Wa2 + bias, via packed fma.rn.f32x2.
// Block: 256 threads = 16x16; tile 64 rows x 128 cols; thread tile 4r x 8c.
// smem: Ws[128][128] (64KB) + Xs[64][128] (32KB) = 96KB; 2 blocks/SM.
#define WS_FLOATS (D * D)
#define XS_FLOATS (64 * D)
__global__ __launch_bounds__(256, 2) void out_gemm_kernel(
    const float* __restrict__ X,
    const float* __restrict__ Wa2,
    float* __restrict__ out, int n) {
    extern __shared__ float sm[];
    float* Ws = sm;               // [k][c], stride 128
    float* Xs = sm + WS_FLOATS;   // [r][k], stride 128

    int tid = threadIdx.x;
    int tx = tid & 15;            // col group: cols [8*tx, 8*tx+8)
    int ty = tid >> 4;            // row group: rows [4*ty, 4*ty+4)
    int row0 = blockIdx.x * 64;

    unsigned long long acc[4][4];
#pragma unroll
    for (int r = 0; r < 4; r++)
#pragma unroll
        for (int c = 0; c < 4; c++) acc[r][c] = 0ull;

    for (int phase = 0; phase < 2; phase++) {
        // stage W (4096 float4 / 256 threads)
        const float4* Wg = (const float4*)(phase == 0 ? g_Wfused : Wa2);
#pragma unroll
        for (int i = tid; i < WS_FLOATS / 4; i += 256)
            ((float4*)Ws)[i] = Wg[i];
        // stage X tile (2048 float4 / 256 threads)
        const float4* Ag = (const float4*)(phase == 0 ? g_agg : X);
#pragma unroll
        for (int i = tid; i < XS_FLOATS / 4; i += 256) {
            int r = row0 + (i >> 5);
            float4 v = make_float4(0.f, 0.f, 0.f, 0.f);
            if (r < n) v = Ag[r * 32 + (i & 31)];
            ((float4*)Xs)[i] = v;
        }
        __syncthreads();

#pragma unroll 4
        for (int k = 0; k < D; k += 2) {
            float2 xv[4];
#pragma unroll
            for (int r = 0; r < 4; r++)
                xv[r] = *(const float2*)&Xs[(ty * 4 + r) * D + k];
#pragma unroll
            for (int kk = 0; kk < 2; kk++) {
                const ulonglong2* wr =
                    (const ulonglong2*)&Ws[(k + kk) * D + tx * 8];
                ulonglong2 wA = wr[0];
                ulonglong2 wB = wr[1];
#pragma unroll
                for (int r = 0; r < 4; r++) {
                    float x = kk ? xv[r].y : xv[r].x;
                    unsigned long long xp;
                    PACKDUP(xp, x);
                    FMA2(acc[r][0], xp, wA.x);
                    FMA2(acc[r][1], xp, wA.y);
                    FMA2(acc[r][2], xp, wB.x);
                    FMA2(acc[r][3], xp, wB.y);
                }
            }
        }
        __syncthreads();
    }

    // bias + store
    const unsigned long long* b2 = (const unsigned long long*)g_bias;
    unsigned long long bp[4];
#pragma unroll
    for (int c = 0; c < 4; c++) bp[c] = b2[tx * 4 + c];

#pragma unroll
    for (int r = 0; r < 4; r++) {
        int row = row0 + ty * 4 + r;
        if (row >= n) break;
#pragma unroll
        for (int c = 0; c < 4; c++) ADD2(acc[r][c], acc[r][c], bp[c]);
        ulonglong2* o2 = (ulonglong2*)(out + row * D + tx * 8);
        o2[0] = make_ulonglong2(acc[r][0], acc[r][1]);
        o2[1] = make_ulonglong2(acc[r][2], acc[r][3]);
    }
}

// ---------------------------------------------------------------------------
extern "C" void kernel_launch(void* const* d_in, const int* in_sizes, int n_in,
                              void* d_out, int out_size) {
    const float* features = (const float*)d_in[0];
    const int*   src      = (const int*)d_in[1];
    const int*   dst      = (const int*)d_in[2];
    const float* W_conv   = (const float*)d_in[3];
    const float* b_conv   = (const float*)d_in[4];
    const float* W_aggr   = (const float*)d_in[5];
    const float* b_aggr   = (const float*)d_in[6];
    float* out = (float*)d_out;

    int n = in_sizes[0] / D;
    int E = in_sizes[1];

    cudaFuncSetAttribute(out_gemm_kernel,
                         cudaFuncAttributeMaxDynamicSharedMemorySize,
                         (WS_FLOATS + XS_FLOATS) * (int)sizeof(float));

    zero_kernel<<<(n + 255) / 256, 256>>>(n);
    deg_kernel<<<(E + 255) / 256, 256>>>(src, dst, E);
    scan_kernel<<<1, 1024>>>(n);
    bucket_kernel<<<(E + 255) / 256, 256>>>(src, dst, E);
    fuse_kernel<<<D + 1, D>>>(W_conv, W_aggr, b_conv, b_aggr);

    aggregate_kernel<<<(n * 32 + 255) / 256, 256>>>(
        (const float4*)features, n);

    int smem = (WS_FLOATS + XS_FLOATS) * (int)sizeof(float);
    out_gemm_kernel<<<(n + 63) / 64, 256, smem>>>(
        features, W_aggr + D * D, out, n);
}

// round 3
// speedup vs baseline: 1.2400x; 1.2400x over previous
#include <cuda_runtime.h>
#include <cstdint>

#define N_MAX 50000
#define D 128

// ---- scratch (__device__ globals; no cudaMalloc allowed) -------------------
__device__ float g_agg[N_MAX * D];     // scatter accumulator [N,128]
__device__ int   g_deg_out[N_MAX];
__device__ int   g_deg_in[N_MAX];
__device__ float g_Wfused[D * D];      // W_conv @ W_aggr[0:128]
__device__ float g_bias[D];            // b_conv @ Wa1 + b_aggr

// packed f32x2 helpers (sm_103a)
#define FMA2(acc, a, b) \
    asm("fma.rn.f32x2 %0, %1, %2, %0;" : "+l"(acc) : "l"(a), "l"(b))
#define ADD2(dst, a, b) \
    asm("add.rn.f32x2 %0, %1, %2;" : "=l"(dst) : "l"(a), "l"(b))
#define PACKDUP(dst, x) \
    asm("mov.b64 %0, {%1, %1};" : "=l"(dst) : "r"(__float_as_uint(x)))

// ---------------------------------------------------------------------------
// K0: zero agg + degree counters
__global__ void zero_kernel(int n) {
    int i = blockIdx.x * blockDim.x + threadIdx.x;
    int nf4 = n * (D / 4);
    if (i < nf4) ((float4*)g_agg)[i] = make_float4(0.f, 0.f, 0.f, 0.f);
    if (i < n) { g_deg_out[i] = 0; g_deg_in[i] = 0; }
}

// K1: degree histograms
__global__ void deg_kernel(const int* __restrict__ src,
                           const int* __restrict__ dst, int E) {
    int i = blockIdx.x * blockDim.x + threadIdx.x;
    if (i < E) {
        atomicAdd(&g_deg_out[src[i]], 1);
        atomicAdd(&g_deg_in[dst[i]], 1);
    }
}

// K2: precompute W_fused = Wc @ Wa1 and bias = b_conv @ Wa1 + b_aggr
__global__ void fuse_kernel(const float* __restrict__ Wc,
                            const float* __restrict__ Wa,
                            const float* __restrict__ bc,
                            const float* __restrict__ ba) {
    int j = threadIdx.x;
    if (blockIdx.x < D) {
        int i = blockIdx.x;
        float s = 0.f;
#pragma unroll 8
        for (int k = 0; k < D; k++) s += Wc[i * D + k] * Wa[k * D + j];
        g_Wfused[i * D + j] = s;
    } else {
        float s = ba[j];
#pragma unroll 8
        for (int k = 0; k < D; k++) s += bc[k] * Wa[k * D + j];
        g_bias[j] = s;
    }
}

// K3: scatter-add: agg[dst[e]] += X[src[e]] * rsqrt(max(deg_out[src[e]],1))
// One warp per edge; each lane moves one float4 (full 512B row per warp).
__global__ __launch_bounds__(256) void scatter_kernel(
    const float4* __restrict__ X4,
    const int* __restrict__ src,
    const int* __restrict__ dst, int E) {
    int gt = blockIdx.x * 256 + threadIdx.x;
    int e = gt >> 5;
    int lane = gt & 31;
    if (e >= E) return;
    int s = __ldg(&src[e]);
    int d = __ldg(&dst[e]);
    float ns = rsqrtf(fmaxf((float)g_deg_out[s], 1.0f));
    float4 v = X4[s * 32 + lane];
    v.x *= ns; v.y *= ns; v.z *= ns; v.w *= ns;
    float4* p = ((float4*)g_agg) + d * 32 + lane;
    asm volatile("red.global.add.v4.f32 [%0], {%1,%2,%3,%4};"
                 :: "l"(p), "f"(v.x), "f"(v.y), "f"(v.z), "f"(v.w)
                 : "memory");
}

// K4: out = (agg * nd) @ W_fused + X @ Wa2 + bias, via packed fma.rn.f32x2.
// Block: 256 threads = 16x16; tile 64 rows x 128 cols; thread tile 4r x 8c.
// smem: Ws[128][128] (64KB) + Xs[64][128] (32KB) = 96KB; 2 blocks/SM.
#define WS_FLOATS (D * D)
#define XS_FLOATS (64 * D)
__global__ __launch_bounds__(256, 2) void out_gemm_kernel(
    const float* __restrict__ X,
    const float* __restrict__ Wa2,
    float* __restrict__ out, int n) {
    extern __shared__ float sm[];
    float* Ws = sm;               // [k][c], stride 128
    float* Xs = sm + WS_FLOATS;   // [r][k], stride 128

    int tid = threadIdx.x;
    int tx = tid & 15;            // col group: cols [8*tx, 8*tx+8)
    int ty = tid >> 4;            // row group: rows [4*ty, 4*ty+4)
    int row0 = blockIdx.x * 64;

    unsigned long long acc[4][4];
#pragma unroll
    for (int r = 0; r < 4; r++)
#pragma unroll
        for (int c = 0; c < 4; c++) acc[r][c] = 0ull;

    for (int phase = 0; phase < 2; phase++) {
        // stage W (4096 float4 / 256 threads)
        const float4* Wg = (const float4*)(phase == 0 ? g_Wfused : Wa2);
#pragma unroll
        for (int i = tid; i < WS_FLOATS / 4; i += 256)
            ((float4*)Ws)[i] = Wg[i];
        // stage X tile (2048 float4 / 256 threads); fold nd into phase 0
        const float4* Ag = (const float4*)(phase == 0 ? g_agg : X);
#pragma unroll
        for (int i = tid; i < XS_FLOATS / 4; i += 256) {
            int r = row0 + (i >> 5);
            float4 v = make_float4(0.f, 0.f, 0.f, 0.f);
            if (r < n) {
                v = Ag[r * 32 + (i & 31)];
                if (phase == 0) {
                    float nd = rsqrtf(fmaxf((float)g_deg_in[r], 1.0f));
                    v.x *= nd; v.y *= nd; v.z *= nd; v.w *= nd;
                }
            }
            ((float4*)Xs)[i] = v;
        }
        __syncthreads();

#pragma unroll 4
        for (int k = 0; k < D; k += 2) {
            float2 xv[4];
#pragma unroll
            for (int r = 0; r < 4; r++)
                xv[r] = *(const float2*)&Xs[(ty * 4 + r) * D + k];
#pragma unroll
            for (int kk = 0; kk < 2; kk++) {
                const ulonglong2* wr =
                    (const ulonglong2*)&Ws[(k + kk) * D + tx * 8];
                ulonglong2 wA = wr[0];
                ulonglong2 wB = wr[1];
#pragma unroll
                for (int r = 0; r < 4; r++) {
                    float x = kk ? xv[r].y : xv[r].x;
                    unsigned long long xp;
                    PACKDUP(xp, x);
                    FMA2(acc[r][0], xp, wA.x);
                    FMA2(acc[r][1], xp, wA.y);
                    FMA2(acc[r][2], xp, wB.x);
                    FMA2(acc[r][3], xp, wB.y);
                }
            }
        }
        __syncthreads();
    }

    // bias + store
    const unsigned long long* b2 = (const unsigned long long*)g_bias;
    unsigned long long bp[4];
#pragma unroll
    for (int c = 0; c < 4; c++) bp[c] = b2[tx * 4 + c];

#pragma unroll
    for (int r = 0; r < 4; r++) {
        int row = row0 + ty * 4 + r;
        if (row >= n) break;
#pragma unroll
        for (int c = 0; c < 4; c++) ADD2(acc[r][c], acc[r][c], bp[c]);
        ulonglong2* o2 = (ulonglong2*)(out + row * D + tx * 8);
        o2[0] = make_ulonglong2(acc[r][0], acc[r][1]);
        o2[1] = make_ulonglong2(acc[r][2], acc[r][3]);
    }
}

// ---------------------------------------------------------------------------
extern "C" void kernel_launch(void* const* d_in, const int* in_sizes, int n_in,
                              void* d_out, int out_size) {
    const float* features = (const float*)d_in[0];
    const int*   src      = (const int*)d_in[1];
    const int*   dst      = (const int*)d_in[2];
    const float* W_conv   = (const float*)d_in[3];
    const float* b_conv   = (const float*)d_in[4];
    const float* W_aggr   = (const float*)d_in[5];
    const float* b_aggr   = (const float*)d_in[6];
    float* out = (float*)d_out;

    int n = in_sizes[0] / D;
    int E = in_sizes[1];

    cudaFuncSetAttribute(out_gemm_kernel,
                         cudaFuncAttributeMaxDynamicSharedMemorySize,
                         (WS_FLOATS + XS_FLOATS) * (int)sizeof(float));

    int nf4 = n * (D / 4);
    zero_kernel<<<(nf4 + 255) / 256, 256>>>(n);
    deg_kernel<<<(E + 255) / 256, 256>>>(src, dst, E);
    fuse_kernel<<<D + 1, D>>>(W_conv, W_aggr, b_conv, b_aggr);

    long long threads = (long long)E * 32;
    scatter_kernel<<<(int)((threads + 255) / 256), 256>>>(
        (const float4*)features, src, dst, E);

    int smem = (WS_FLOATS + XS_FLOATS) * (int)sizeof(float);
    out_gemm_kernel<<<(n + 63) / 64, 256, smem>>>(
        features, W_aggr + D * D, out, n);
}

// round 4
// speedup vs baseline: 1.7460x; 1.4081x over previous
#include <cuda_runtime.h>
#include <cuda_bf16.h>
#include <cstdint>

#define N_MAX 50000
#define D 128

// ---- scratch (__device__ globals; no cudaMalloc allowed) -------------------
__device__ float g_agg[N_MAX * D];     // scatter accumulator [N,128]
__device__ int   g_deg_out[N_MAX];
__device__ int   g_deg_in[N_MAX];
__device__ float g_ns[N_MAX];          // rsqrt(max(deg_out,1))
__device__ float g_nd[N_MAX];          // rsqrt(max(deg_in,1))
__device__ float g_Wfused[D * D];      // W_conv @ W_aggr[0:128]
__device__ float g_bias[D];            // b_conv @ Wa1 + b_aggr

// ---------------------------------------------------------------------------
// K0: zero agg + degree counters
__global__ void zero_kernel(int n) {
    int i = blockIdx.x * blockDim.x + threadIdx.x;
    int nf4 = n * (D / 4);
    if (i < nf4) ((float4*)g_agg)[i] = make_float4(0.f, 0.f, 0.f, 0.f);
    if (i < n) { g_deg_out[i] = 0; g_deg_in[i] = 0; }
}

// K1: degree histograms
__global__ void deg_kernel(const int* __restrict__ src,
                           const int* __restrict__ dst, int E) {
    int i = blockIdx.x * blockDim.x + threadIdx.x;
    if (i < E) {
        atomicAdd(&g_deg_out[src[i]], 1);
        atomicAdd(&g_deg_in[dst[i]], 1);
    }
}

// K2: normalization factors
__global__ void norm_kernel(int n) {
    int i = blockIdx.x * blockDim.x + threadIdx.x;
    if (i < n) {
        g_ns[i] = rsqrtf(fmaxf((float)g_deg_out[i], 1.0f));
        g_nd[i] = rsqrtf(fmaxf((float)g_deg_in[i], 1.0f));
    }
}

// K3: W_fused = Wc @ Wa1, bias = b_conv @ Wa1 + b_aggr
__global__ void fuse_kernel(const float* __restrict__ Wc,
                            const float* __restrict__ Wa,
                            const float* __restrict__ bc,
                            const float* __restrict__ ba) {
    int j = threadIdx.x;
    if (blockIdx.x < D) {
        int i = blockIdx.x;
        float s = 0.f;
#pragma unroll 8
        for (int k = 0; k < D; k++) s += Wc[i * D + k] * Wa[k * D + j];
        g_Wfused[i * D + j] = s;
    } else {
        float s = ba[j];
#pragma unroll 8
        for (int k = 0; k < D; k++) s += bc[k] * Wa[k * D + j];
        g_bias[j] = s;
    }
}

// K4: scatter-add: agg[dst[e]] += X[src[e]] * ns[src[e]]  (one warp per edge)
__global__ __launch_bounds__(256) void scatter_kernel(
    const float4* __restrict__ X4,
    const int* __restrict__ src,
    const int* __restrict__ dst, int E) {
    int gt = blockIdx.x * 256 + threadIdx.x;
    int e = gt >> 5;
    int lane = gt & 31;
    if (e >= E) return;
    int s = __ldg(&src[e]);
    int d = __ldg(&dst[e]);
    float ns = g_ns[s];
    float4 v = X4[s * 32 + lane];
    v.x *= ns; v.y *= ns; v.z *= ns; v.w *= ns;
    float4* p = ((float4*)g_agg) + d * 32 + lane;
    asm volatile("red.global.add.v4.f32 [%0], {%1,%2,%3,%4};"
                 :: "l"(p), "f"(v.x), "f"(v.y), "f"(v.z), "f"(v.w)
                 : "memory");
}

// ---------------------------------------------------------------------------
// K5: tensor-core GEMM: out = (agg*nd) @ W_fused + X @ Wa2 + bias
// bf16 error-compensated split, fp32 accumulate, mma.m16n8k16.
// Block tile 128m x 128n, K=256 in 4 chunks of 64. 8 warps (2m x 4n),
// warp tile 64m x 32n -> 4x4 m16n8 atoms, 64 fp32 acc regs/thread.
#define KC 64
#define KPC (KC / 2)       // kpairs per chunk = 32
#define A_STR 33           // sA row stride (u32), pad for bank-free frag reads
#define B_STR 136          // sB row stride (u32), 136 % 32 == 8 -> bank-free
#define SA_SZ (128 * A_STR)
#define SB_SZ (KPC * B_STR)
#define SM_U32 (2 * SA_SZ + 2 * SB_SZ)

#define MMA_BF16(c, a, b)                                                   \
    asm volatile(                                                           \
        "mma.sync.aligned.m16n8k16.row.col.f32.bf16.bf16.f32 "              \
        "{%0,%1,%2,%3}, {%4,%5,%6,%7}, {%8,%9}, {%0,%1,%2,%3};"             \
        : "+f"((c)[0]), "+f"((c)[1]), "+f"((c)[2]), "+f"((c)[3])            \
        : "r"((a)[0]), "r"((a)[1]), "r"((a)[2]), "r"((a)[3]),               \
          "r"((b)[0]), "r"((b)[1]))

__device__ __forceinline__ void split_pack(float v0, float v1,
                                           unsigned& hi, unsigned& lo) {
    __nv_bfloat162 h, l;
    h.x = __float2bfloat16(v0);
    h.y = __float2bfloat16(v1);
    l.x = __float2bfloat16(v0 - __bfloat162float(h.x));
    l.y = __float2bfloat16(v1 - __bfloat162float(h.y));
    hi = *(unsigned*)&h;
    lo = *(unsigned*)&l;
}

__global__ __launch_bounds__(256) void out_gemm_kernel(
    const float* __restrict__ X,
    const float* __restrict__ Wa2,
    float* __restrict__ out, int n) {
    extern __shared__ unsigned sm[];
    unsigned* sAh = sm;
    unsigned* sAl = sm + SA_SZ;
    unsigned* sBh = sm + 2 * SA_SZ;
    unsigned* sBl = sm + 2 * SA_SZ + SB_SZ;

    int tid = threadIdx.x;
    int wid = tid >> 5;
    int lane = tid & 31;
    int gid = lane >> 2;     // 0..7
    int tig = lane & 3;      // 0..3
    int wm = wid >> 2;       // 0..1  -> rows 64*wm
    int wn = wid & 3;        // 0..3  -> cols 32*wn
    int row0 = blockIdx.x * 128;

    float acc[4][4][4];
#pragma unroll
    for (int mt = 0; mt < 4; mt++)
#pragma unroll
        for (int nt = 0; nt < 4; nt++)
#pragma unroll
            for (int i = 0; i < 4; i++) acc[mt][nt][i] = 0.f;

#pragma unroll
    for (int phase = 0; phase < 2; phase++) {
        const float* Asrc = (phase == 0) ? g_agg : X;
        const float* Wsrc = (phase == 0) ? g_Wfused : Wa2;
#pragma unroll
        for (int ch = 0; ch < 2; ch++) {
            int k0 = ch * KC;
            // ---- stage A: 128 rows x 64 cols -> packed bf16 pairs --------
            // idx: r = idx>>4 (row), f4 = idx&15 (float4 within 64 cols)
#pragma unroll
            for (int it = 0; it < 8; it++) {
                int idx = tid + it * 256;
                int r = idx >> 4;
                int f4 = idx & 15;
                int grow = row0 + r;
                float4 v = make_float4(0.f, 0.f, 0.f, 0.f);
                if (grow < n) {
                    v = ((const float4*)Asrc)[grow * 32 + (k0 >> 2) + f4];
                    if (phase == 0) {
                        float nd = g_nd[grow];
                        v.x *= nd; v.y *= nd; v.z *= nd; v.w *= nd;
                    }
                }
                unsigned h0, l0, h1, l1;
                split_pack(v.x, v.y, h0, l0);
                split_pack(v.z, v.w, h1, l1);
                int o = r * A_STR + f4 * 2;
                sAh[o] = h0; sAh[o + 1] = h1;
                sAl[o] = l0; sAl[o + 1] = l1;
            }
            // ---- stage B: 64 k x 128 n -> packed [kpair][n] ---------------
            // idx: kp = idx>>7, nn = idx&127
#pragma unroll
            for (int it = 0; it < 16; it++) {
                int idx = tid + it * 256;
                int kp = idx >> 7;
                int nn = idx & 127;
                float w0 = Wsrc[(k0 + 2 * kp) * D + nn];
                float w1 = Wsrc[(k0 + 2 * kp + 1) * D + nn];
                unsigned h, l;
                split_pack(w0, w1, h, l);
                sBh[kp * B_STR + nn] = h;
                sBl[kp * B_STR + nn] = l;
            }
            __syncthreads();

            // ---- mma over 4 k16 steps ------------------------------------
#pragma unroll
            for (int s = 0; s < 4; s++) {
                int kb = s * 8;  // kpair base
                unsigned bh[4][2], bl[4][2];
#pragma unroll
                for (int nt = 0; nt < 4; nt++) {
                    int col = wn * 32 + nt * 8 + gid;
                    bh[nt][0] = sBh[(kb + tig) * B_STR + col];
                    bh[nt][1] = sBh[(kb + tig + 4) * B_STR + col];
                    bl[nt][0] = sBl[(kb + tig) * B_STR + col];
                    bl[nt][1] = sBl[(kb + tig + 4) * B_STR + col];
                }
#pragma unroll
                for (int mt = 0; mt < 4; mt++) {
                    int rb = wm * 64 + mt * 16;
                    unsigned ah[4], al[4];
                    ah[0] = sAh[(rb + gid) * A_STR + kb + tig];
                    ah[1] = sAh[(rb + gid + 8) * A_STR + kb + tig];
                    ah[2] = sAh[(rb + gid) * A_STR + kb + tig + 4];
                    ah[3] = sAh[(rb + gid + 8) * A_STR + kb + tig + 4];
                    al[0] = sAl[(rb + gid) * A_STR + kb + tig];
                    al[1] = sAl[(rb + gid + 8) * A_STR + kb + tig];
                    al[2] = sAl[(rb + gid) * A_STR + kb + tig + 4];
                    al[3] = sAl[(rb + gid + 8) * A_STR + kb + tig + 4];
#pragma unroll
                    for (int nt = 0; nt < 4; nt++) {
                        MMA_BF16(acc[mt][nt], ah, bh[nt]);  // hi*hi
                        MMA_BF16(acc[mt][nt], ah, bl[nt]);  // hi*lo
                        MMA_BF16(acc[mt][nt], al, bh[nt]);  // lo*hi
                    }
                }
            }
            __syncthreads();
        }
    }

    // ---- epilogue: bias + store ------------------------------------------
#pragma unroll
    for (int mt = 0; mt < 4; mt++) {
        int r = row0 + wm * 64 + mt * 16 + gid;
#pragma unroll
        for (int nt = 0; nt < 4; nt++) {
            int col = wn * 32 + nt * 8 + 2 * tig;
            float2 bv = *(const float2*)&g_bias[col];
            if (r < n) {
                float2 o0 = make_float2(acc[mt][nt][0] + bv.x,
                                        acc[mt][nt][1] + bv.y);
                *(float2*)&out[r * D + col] = o0;
            }
            if (r + 8 < n) {
                float2 o1 = make_float2(acc[mt][nt][2] + bv.x,
                                        acc[mt][nt][3] + bv.y);
                *(float2*)&out[(r + 8) * D + col] = o1;
            }
        }
    }
}

// ---------------------------------------------------------------------------
extern "C" void kernel_launch(void* const* d_in, const int* in_sizes, int n_in,
                              void* d_out, int out_size) {
    const float* features = (const float*)d_in[0];
    const int*   src      = (const int*)d_in[1];
    const int*   dst      = (const int*)d_in[2];
    const float* W_conv   = (const float*)d_in[3];
    const float* b_conv   = (const float*)d_in[4];
    const float* W_aggr   = (const float*)d_in[5];
    const float* b_aggr   = (const float*)d_in[6];
    float* out = (float*)d_out;

    int n = in_sizes[0] / D;
    int E = in_sizes[1];

    cudaFuncSetAttribute(out_gemm_kernel,
                         cudaFuncAttributeMaxDynamicSharedMemorySize,
                         SM_U32 * (int)sizeof(unsigned));

    int nf4 = n * (D / 4);
    zero_kernel<<<(nf4 + 255) / 256, 256>>>(n);
    deg_kernel<<<(E + 255) / 256, 256>>>(src, dst, E);
    norm_kernel<<<(n + 255) / 256, 256>>>(n);
    fuse_kernel<<<D + 1, D>>>(W_conv, W_aggr, b_conv, b_aggr);

    long long threads = (long long)E * 32;
    scatter_kernel<<<(int)((threads + 255) / 256), 256>>>(
        (const float4*)features, src, dst, E);

    out_gemm_kernel<<<(n + 127) / 128, 256, SM_U32 * (int)sizeof(unsigned)>>>(
        features, W_aggr + D * D, out, n);
}